// round 6
// baseline (speedup 1.0000x reference)
#include <cuda_runtime.h>
#include <stdint.h>

// Problem shape (fixed by the dataset)
#define BATCH   8192
#define IN_DIM  4096
#define N_RULES 2048
#define KWORDS  (IN_DIM / 32)     // 128 u32 bit-words along k
#define ROWS_PB 16                // rows per out-block
#define RBLOCKS 8                 // blocks in wany_reduce

// Scratch (device globals — no allocation allowed)
__device__ uint32_t g_wbits[N_RULES * KWORDS];   // [r][w]
__device__ uint32_t g_abits[BATCH   * KWORDS];   // [b][w]
__device__ uint32_t g_wany [N_RULES];            // final OR of rule r's words
__device__ uint32_t g_aflag[BATCH];              // 1 if row b has exact x==1.0f
__device__ uint32_t g_anyblk[RBLOCKS];           // per-reduce-block OR summary
                                                 // (always written -> no init)

// ---------------------------------------------------------------------------
// Kernel 1: pack W > 0.5, one thread per 32-bit output word. No smem, no
// sync, max occupancy. Lanes map to consecutive rules r, so each of the 32
// k-loads is a fully coalesced 128B transaction.
// ---------------------------------------------------------------------------
__global__ __launch_bounds__(256) void pack_w_kernel(const float* __restrict__ W) {
    int idx = blockIdx.x * blockDim.x + threadIdx.x;   // [0, N_RULES*KWORDS)
    int r = idx & (N_RULES - 1);
    int w = idx >> 11;                                  // log2(N_RULES) = 11
    const float* p = W + (size_t)(w * 32) * N_RULES + r;
    uint32_t word = 0;
#pragma unroll
    for (int j = 0; j < 32; j++) {
        if (p[(size_t)j * N_RULES] > 0.5f) word |= (1u << j);
    }
    g_wbits[r * KWORDS + w] = word;
}

// ---------------------------------------------------------------------------
// Kernel 2: wany reduction. One thread per rule ORs its 128 words (512B,
// L2-resident). Also writes per-block any-summaries for pack_x's early exit.
// ---------------------------------------------------------------------------
__global__ __launch_bounds__(256) void wany_reduce_kernel() {
    int r = blockIdx.x * blockDim.x + threadIdx.x;     // [0, N_RULES)
    const uint4* p = reinterpret_cast<const uint4*>(g_wbits + r * KWORDS);
    uint32_t o = 0;
#pragma unroll 8
    for (int i = 0; i < KWORDS / 4; i++) {
        uint4 v = p[i];
        o |= v.x | v.y | v.z | v.w;
    }
    g_wany[r] = o;
    uint32_t blk = __syncthreads_or(o != 0u) ? 1u : 0u;
    if (threadIdx.x == 0) g_anyblk[blockIdx.x] = blk;  // always written
}

// ---------------------------------------------------------------------------
// Kernel 3: pack x. EARLY EXIT: if every rule is empty, abits/aflag can never
// be consumed by out_kernel, so skip the 128MB read entirely. Otherwise:
// block owns one row; each warp packs 512 consecutive elements via ballot.
// ---------------------------------------------------------------------------
__global__ __launch_bounds__(256) void pack_x_kernel(const float* __restrict__ x) {
    uint32_t rs = (threadIdx.x < RBLOCKS) ? g_anyblk[threadIdx.x] : 0u;
    if (!__syncthreads_or(rs != 0u)) return;           // dominant: all empty

    __shared__ uint32_t sm_ok[8];
    int wi   = threadIdx.x >> 5;
    int lane = threadIdx.x & 31;
    int b = blockIdx.x;
    const float* px = x + (size_t)b * IN_DIM + wi * 512;
    uint32_t wrd[16];
    uint32_t ones = 0xFFFFFFFFu;
#pragma unroll
    for (int u = 0; u < 16; u++) {
        float v = px[u * 32 + lane];                   // coalesced 128B line
        wrd[u] = __ballot_sync(0xFFFFFFFFu, v != 1.0f);
        ones &= wrd[u];
    }
    if (lane == 0) {
        uint4* q = reinterpret_cast<uint4*>(g_abits + b * KWORDS + wi * 16);
        q[0] = make_uint4(wrd[0],  wrd[1],  wrd[2],  wrd[3]);
        q[1] = make_uint4(wrd[4],  wrd[5],  wrd[6],  wrd[7]);
        q[2] = make_uint4(wrd[8],  wrd[9],  wrd[10], wrd[11]);
        q[3] = make_uint4(wrd[12], wrd[13], wrd[14], wrd[15]);
        sm_ok[wi] = (ones == 0xFFFFFFFFu) ? 1u : 0u;
    }
    __syncthreads();
    if (threadIdx.x == 0) {
        uint32_t a = sm_ok[0] & sm_ok[1] & sm_ok[2] & sm_ok[3] &
                     sm_ok[4] & sm_ok[5] & sm_ok[6] & sm_ok[7];
        g_aflag[b] = a ? 0u : 1u;                      // 1 <=> row has exact 1.0
    }
}

// Rare general path: any weight-selected k with x[b,k] != 1 makes res > 0.
__device__ __forceinline__ float conj_general(int b, int r) {
    const uint32_t* A  = g_abits + b * KWORDS;
    const uint32_t* Wp = g_wbits + r * KWORDS;
    for (int i = 0; i < KWORDS; i++) {
        if (A[i] & Wp[i]) return 0.0f;
    }
    return 1.0f;
}

// ---------------------------------------------------------------------------
// Kernel 4: output [BATCH, N_RULES]. Thread owns one 4-rule group, reads its
// final wany uint4 ONCE, streams ROWS_PB rows of coalesced float4 writes.
// aflag/abits are read only when the group is non-empty (=> pack_x ran).
// ---------------------------------------------------------------------------
__global__ __launch_bounds__(256) void out_kernel(float* __restrict__ out) {
    int g  = (blockIdx.x & 1) * 256 + threadIdx.x;     // group in [0, 512)
    int b0 = (blockIdx.x >> 1) * ROWS_PB;
    int lane = threadIdx.x & 31;

    uint4 w4 = reinterpret_cast<const uint4*>(g_wany)[g];
    bool empty = (w4.x | w4.y | w4.z | w4.w) == 0u;

    float4 val0;                                       // aflag==0 answer
    val0.x = (w4.x == 0u) ? 1.0f : 0.0f;
    val0.y = (w4.y == 0u) ? 1.0f : 0.0f;
    val0.z = (w4.z == 0u) ? 1.0f : 0.0f;
    val0.w = (w4.w == 0u) ? 1.0f : 0.0f;

    uint32_t af_l = 0u;
    if (!empty && lane < ROWS_PB) af_l = g_aflag[b0 + lane];

    float4* o4 = reinterpret_cast<float4*>(out) + (size_t)b0 * 512 + g;
#pragma unroll
    for (int r = 0; r < ROWS_PB; r++) {
        uint32_t afr = __shfl_sync(0xFFFFFFFFu, af_l, r);
        float4 o;
        if (empty || !afr) {
            o = val0;                                  // dominant path
        } else {
            int b  = b0 + r;
            int r0 = g * 4;
            o.x = (w4.x == 0u) ? 1.0f : conj_general(b, r0 + 0);
            o.y = (w4.y == 0u) ? 1.0f : conj_general(b, r0 + 1);
            o.z = (w4.z == 0u) ? 1.0f : conj_general(b, r0 + 2);
            o.w = (w4.w == 0u) ? 1.0f : conj_general(b, r0 + 3);
        }
        o4[(size_t)r * 512] = o;
    }
}

// ---------------------------------------------------------------------------
extern "C" void kernel_launch(void* const* d_in, const int* in_sizes, int n_in,
                              void* d_out, int out_size) {
    const float* x = (const float*)d_in[0];   // [BATCH, IN_DIM]
    const float* W = (const float*)d_in[1];   // [IN_DIM, N_RULES]
    float* out = (float*)d_out;               // [BATCH, N_RULES]

    (void)in_sizes; (void)n_in; (void)out_size;

    pack_w_kernel<<<(N_RULES * KWORDS) / 256, 256>>>(W);   // 1024 blocks
    wany_reduce_kernel<<<RBLOCKS, 256>>>();                // 8 blocks
    pack_x_kernel<<<BATCH, 256>>>(x);                      // 8192 (early exit)
    out_kernel<<<2 * (BATCH / ROWS_PB), 256>>>(out);       // 1024 blocks
}

// round 7
// speedup vs baseline: 1.4542x; 1.4542x over previous
#include <cuda_runtime.h>
#include <stdint.h>

// Problem shape (fixed by the dataset)
#define BATCH   8192
#define IN_DIM  4096
#define N_RULES 2048
#define KWORDS  (IN_DIM / 32)     // 128 u32 bit-words along k
#define NSPLIT  8                 // k-splits for pack_w partial wany
#define WBLOCKS (NSPLIT * (N_RULES / 32))   // 512 pack_w blocks
#define XROWS   8                 // rows per pack_x block

// Scratch (device globals — no allocation allowed)
__device__ uint32_t g_wbits[N_RULES * KWORDS];   // [r][w]
__device__ uint32_t g_abits[BATCH   * KWORDS];   // [b][w]
__device__ uint32_t g_wany8[NSPLIT * N_RULES];   // per-split OR of rule words
__device__ uint32_t g_aflag[BATCH];              // 1 if row b has exact x==1.0f
__device__ uint32_t g_rsum [WBLOCKS];            // per-pack_w-block OR summary
                                                 // (always written -> no init)

// ---------------------------------------------------------------------------
// Kernel 1: pack W > 0.5 + fused partial wany. Block owns 32 rules x 512
// k-values (one of 8 splits). Lanes span consecutive rules -> every k-load is
// a fully coalesced 128B transaction. 512 blocks => ~28 warps/SM of MLP.
// ---------------------------------------------------------------------------
__global__ __launch_bounds__(256) void pack_w_kernel(const float* __restrict__ W) {
    __shared__ uint32_t sm_red[8][32];
    int wi   = threadIdx.x >> 5;
    int lane = threadIdx.x & 31;
    int s     = blockIdx.x;             // [0, WBLOCKS)
    int split = s & (NSPLIT - 1);
    int r     = (s >> 3) * 32 + lane;   // s / NSPLIT * 32 + lane

    uint32_t acc = 0;
#pragma unroll
    for (int t = 0; t < 2; t++) {
        int w = split * 16 + t * 8 + wi;
        const float* p = W + (size_t)(w * 32) * N_RULES + r;
        uint32_t word = 0;
#pragma unroll
        for (int j = 0; j < 32; j++) {
            if (p[(size_t)j * N_RULES] > 0.5f) word |= (1u << j);
        }
        g_wbits[r * KWORDS + w] = word;
        acc |= word;
    }
    sm_red[wi][lane] = acc;
    __syncthreads();
    if (wi == 0) {
        uint32_t o = sm_red[0][lane] | sm_red[1][lane] | sm_red[2][lane] |
                     sm_red[3][lane] | sm_red[4][lane] | sm_red[5][lane] |
                     sm_red[6][lane] | sm_red[7][lane];
        g_wany8[split * N_RULES + r] = o;
        uint32_t blk = __reduce_or_sync(0xFFFFFFFFu, o);
        if (lane == 0) g_rsum[s] = blk;   // always written each replay
    }
}

// ---------------------------------------------------------------------------
// Kernel 2: pack x, XROWS rows per block. EARLY EXIT: if every rule is empty
// (all g_rsum == 0), abits/aflag can never be consumed, so skip the 128MB
// read. Check costs one uint2 load per thread (2KB/block).
// ---------------------------------------------------------------------------
__global__ __launch_bounds__(256) void pack_x_kernel(const float* __restrict__ x) {
    uint2 rs = reinterpret_cast<const uint2*>(g_rsum)[threadIdx.x]; // 256*2=512
    if (!__syncthreads_or((rs.x | rs.y) != 0u)) return;  // dominant: all empty

    __shared__ uint32_t sm_ok[8];
    int wi   = threadIdx.x >> 5;
    int lane = threadIdx.x & 31;

    for (int i = 0; i < XROWS; i++) {
        int b = blockIdx.x * XROWS + i;
        const float* px = x + (size_t)b * IN_DIM + wi * 512;
        uint32_t wrd[16];
        uint32_t ones = 0xFFFFFFFFu;
#pragma unroll
        for (int u = 0; u < 16; u++) {
            float v = px[u * 32 + lane];                 // coalesced 128B line
            wrd[u] = __ballot_sync(0xFFFFFFFFu, v != 1.0f);
            ones &= wrd[u];
        }
        if (lane == 0) {
            uint4* q = reinterpret_cast<uint4*>(g_abits + b * KWORDS + wi * 16);
            q[0] = make_uint4(wrd[0],  wrd[1],  wrd[2],  wrd[3]);
            q[1] = make_uint4(wrd[4],  wrd[5],  wrd[6],  wrd[7]);
            q[2] = make_uint4(wrd[8],  wrd[9],  wrd[10], wrd[11]);
            q[3] = make_uint4(wrd[12], wrd[13], wrd[14], wrd[15]);
            sm_ok[wi] = (ones == 0xFFFFFFFFu) ? 1u : 0u;
        }
        __syncthreads();
        if (threadIdx.x == 0) {
            uint32_t a = sm_ok[0] & sm_ok[1] & sm_ok[2] & sm_ok[3] &
                         sm_ok[4] & sm_ok[5] & sm_ok[6] & sm_ok[7];
            g_aflag[b] = a ? 0u : 1u;                    // 1 <=> row has exact 1.0
        }
        __syncthreads();
    }
}

// Rare general path: any weight-selected k with x[b,k] != 1 makes res > 0.
__device__ __forceinline__ float conj_general(int b, int r) {
    const uint32_t* A  = g_abits + b * KWORDS;
    const uint32_t* Wp = g_wbits + r * KWORDS;
    for (int i = 0; i < KWORDS; i++) {
        if (A[i] & Wp[i]) return 0.0f;
    }
    return 1.0f;
}

// ---------------------------------------------------------------------------
// Kernel 3: output. Block owns 32 rules x 512 rows: folds the 8 wany partials
// ONCE per block into smem (1MB total L2 traffic), then streams coalesced
// float4 writes (warp covers 4 rows x 128B lines). Grid 64 x 16 = 1024 blocks.
// ---------------------------------------------------------------------------
__global__ __launch_bounds__(256) void out_kernel(float* __restrict__ out) {
    __shared__ __align__(16) float s_val[32];   // aflag==0 answer per rule
    __shared__ uint32_t s_w[32];                // folded wany per rule
    __shared__ uint32_t s_empty;
    int tid = threadIdx.x;
    int rg  = blockIdx.x & 63;                  // rule-group: 32 rules
    int b0  = (blockIdx.x >> 6) * 512;          // row-slice base

    if (tid < 32) {
        int r = rg * 32 + tid;
        uint32_t o = 0;
#pragma unroll
        for (int s = 0; s < NSPLIT; s++) o |= g_wany8[s * N_RULES + r];
        s_w[tid]   = o;
        s_val[tid] = (o == 0u) ? 1.0f : 0.0f;
        uint32_t any = __reduce_or_sync(0xFFFFFFFFu, o);
        if (tid == 0) s_empty = (any == 0u) ? 1u : 0u;
    }
    __syncthreads();

    bool empty  = (s_empty != 0u);
    int  chunk  = tid & 7;                      // float4 chunk within 32 rules
    int  rowoff = tid >> 3;                     // 0..31
    float4 v0 = reinterpret_cast<const float4*>(s_val)[chunk];
    float4* o4 = reinterpret_cast<float4*>(out);

#pragma unroll
    for (int it = 0; it < 16; it++) {
        int b = b0 + it * 32 + rowoff;
        float4 o;
        if (empty || !g_aflag[b]) {
            o = v0;                             // dominant path
        } else {
            int r0 = rg * 32 + chunk * 4;
            o.x = (s_w[chunk*4+0] == 0u) ? 1.0f : conj_general(b, r0 + 0);
            o.y = (s_w[chunk*4+1] == 0u) ? 1.0f : conj_general(b, r0 + 1);
            o.z = (s_w[chunk*4+2] == 0u) ? 1.0f : conj_general(b, r0 + 2);
            o.w = (s_w[chunk*4+3] == 0u) ? 1.0f : conj_general(b, r0 + 3);
        }
        o4[(size_t)b * 512 + rg * 8 + chunk] = o;
    }
}

// ---------------------------------------------------------------------------
extern "C" void kernel_launch(void* const* d_in, const int* in_sizes, int n_in,
                              void* d_out, int out_size) {
    const float* x = (const float*)d_in[0];   // [BATCH, IN_DIM]
    const float* W = (const float*)d_in[1];   // [IN_DIM, N_RULES]
    float* out = (float*)d_out;               // [BATCH, N_RULES]

    (void)in_sizes; (void)n_in; (void)out_size;

    pack_w_kernel<<<WBLOCKS, 256>>>(W);            // 512 blocks
    pack_x_kernel<<<BATCH / XROWS, 256>>>(x);      // 1024 blocks (early exit)
    out_kernel<<<64 * 16, 256>>>(out);             // 1024 blocks
}

// round 8
// speedup vs baseline: 1.4562x; 1.0014x over previous
#include <cuda_runtime.h>
#include <stdint.h>

// Problem shape (fixed by the dataset)
#define BATCH   8192
#define IN_DIM  4096
#define N_RULES 2048
#define KWORDS  (IN_DIM / 32)     // 128 u32 bit-words along k
#define NSPLIT  16                // k-splits for pack_w partial wany
#define WBLOCKS (NSPLIT * (N_RULES / 128))  // 256 pack_w blocks
#define XROWS   8                 // rows per pack_x block

// Scratch (device globals — no allocation allowed)
__device__ uint32_t g_wbitsT[KWORDS * N_RULES];   // TRANSPOSED: [w][r]
__device__ uint32_t g_abits [BATCH  * KWORDS];    // [b][w]
__device__ uint32_t g_wany16[NSPLIT * N_RULES];   // per-split OR of rule words
__device__ uint32_t g_aflag [BATCH];              // 1 if row b has exact x==1.0f
__device__ uint32_t g_rsum  [WBLOCKS];            // per-block OR summary
                                                  // (always written -> no init)

// ---------------------------------------------------------------------------
// Kernel 1: pack W > 0.5 + fused partial wany. Each lane owns 4 consecutive
// rules (float4 loads: warp = 512 contiguous bytes per k -> LDG.128,
// 4x in-flight bytes vs scalar). Block = 128 rules x 8 words (one of 16
// k-splits). Bit-words stored TRANSPOSED [w][r] so stores are coalesced uint4.
// ---------------------------------------------------------------------------
__global__ __launch_bounds__(256) void pack_w_kernel(const float* __restrict__ W) {
    __shared__ uint4 sm_red[8][32];
    int wi   = threadIdx.x >> 5;
    int lane = threadIdx.x & 31;
    int s     = blockIdx.x;               // [0, 256)
    int split = s & (NSPLIT - 1);
    int rq    = (s >> 4) * 32 + lane;     // rule-quad index [0, 512)
    int w     = split * 8 + wi;           // word index [0, 128)

    const float4* W4 = reinterpret_cast<const float4*>(W);
    uint32_t w0 = 0, w1 = 0, w2 = 0, w3 = 0;
#pragma unroll
    for (int j = 0; j < 32; j++) {
        float4 v = W4[(size_t)(w * 32 + j) * (N_RULES / 4) + rq];
        uint32_t bit = 1u << j;
        if (v.x > 0.5f) w0 |= bit;
        if (v.y > 0.5f) w1 |= bit;
        if (v.z > 0.5f) w2 |= bit;
        if (v.w > 0.5f) w3 |= bit;
    }
    uint4 words = make_uint4(w0, w1, w2, w3);
    reinterpret_cast<uint4*>(g_wbitsT + (size_t)w * N_RULES)[rq] = words;

    sm_red[wi][lane] = words;
    __syncthreads();
    if (wi == 0) {
        uint4 o = sm_red[0][lane];
#pragma unroll
        for (int k = 1; k < 8; k++) {
            uint4 v = sm_red[k][lane];
            o.x |= v.x; o.y |= v.y; o.z |= v.z; o.w |= v.w;
        }
        reinterpret_cast<uint4*>(g_wany16 + split * N_RULES)[rq] = o;
        uint32_t any = __reduce_or_sync(0xFFFFFFFFu, o.x | o.y | o.z | o.w);
        if (lane == 0) g_rsum[s] = any;   // always written each replay
    }
}

// ---------------------------------------------------------------------------
// Kernel 2: pack x, XROWS rows per block. EARLY EXIT: if every rule is empty
// (all g_rsum == 0), abits/aflag can never be consumed -> skip the 128MB read.
// ---------------------------------------------------------------------------
__global__ __launch_bounds__(256) void pack_x_kernel(const float* __restrict__ x) {
    uint32_t rs = g_rsum[threadIdx.x];                  // WBLOCKS == 256
    if (!__syncthreads_or(rs != 0u)) return;            // dominant: all empty

    __shared__ uint32_t sm_ok[8];
    int wi   = threadIdx.x >> 5;
    int lane = threadIdx.x & 31;

    for (int i = 0; i < XROWS; i++) {
        int b = blockIdx.x * XROWS + i;
        const float* px = x + (size_t)b * IN_DIM + wi * 512;
        uint32_t wrd[16];
        uint32_t ones = 0xFFFFFFFFu;
#pragma unroll
        for (int u = 0; u < 16; u++) {
            float v = px[u * 32 + lane];                // coalesced 128B line
            wrd[u] = __ballot_sync(0xFFFFFFFFu, v != 1.0f);
            ones &= wrd[u];
        }
        if (lane == 0) {
            uint4* q = reinterpret_cast<uint4*>(g_abits + b * KWORDS + wi * 16);
            q[0] = make_uint4(wrd[0],  wrd[1],  wrd[2],  wrd[3]);
            q[1] = make_uint4(wrd[4],  wrd[5],  wrd[6],  wrd[7]);
            q[2] = make_uint4(wrd[8],  wrd[9],  wrd[10], wrd[11]);
            q[3] = make_uint4(wrd[12], wrd[13], wrd[14], wrd[15]);
            sm_ok[wi] = (ones == 0xFFFFFFFFu) ? 1u : 0u;
        }
        __syncthreads();
        if (threadIdx.x == 0) {
            uint32_t a = sm_ok[0] & sm_ok[1] & sm_ok[2] & sm_ok[3] &
                         sm_ok[4] & sm_ok[5] & sm_ok[6] & sm_ok[7];
            g_aflag[b] = a ? 0u : 1u;                   // 1 <=> row has exact 1.0
        }
        __syncthreads();
    }
}

// Rare general path: any weight-selected k with x[b,k] != 1 makes res > 0.
// (wbits is transposed; strided reads are fine on this cold path.)
__device__ __forceinline__ float conj_general(int b, int r) {
    const uint32_t* A = g_abits + b * KWORDS;
    for (int i = 0; i < KWORDS; i++) {
        if (A[i] & g_wbitsT[(size_t)i * N_RULES + r]) return 0.0f;
    }
    return 1.0f;
}

// ---------------------------------------------------------------------------
// Kernel 3: output. Block owns 32 rules x 512 rows: folds the 16 wany
// partials ONCE per block into smem, then streams coalesced float4 writes.
// Grid 64 x 16 = 1024 blocks. aflag/abits read only when group non-empty.
// ---------------------------------------------------------------------------
__global__ __launch_bounds__(256) void out_kernel(float* __restrict__ out) {
    __shared__ __align__(16) float s_val[32];   // aflag==0 answer per rule
    __shared__ uint32_t s_w[32];                // folded wany per rule
    __shared__ uint32_t s_empty;
    int tid = threadIdx.x;
    int rg  = blockIdx.x & 63;                  // rule-group: 32 rules
    int b0  = (blockIdx.x >> 6) * 512;          // row-slice base

    if (tid < 32) {
        int r = rg * 32 + tid;
        uint32_t o = 0;
#pragma unroll
        for (int s = 0; s < NSPLIT; s++) o |= g_wany16[s * N_RULES + r];
        s_w[tid]   = o;
        s_val[tid] = (o == 0u) ? 1.0f : 0.0f;
        uint32_t any = __reduce_or_sync(0xFFFFFFFFu, o);
        if (tid == 0) s_empty = (any == 0u) ? 1u : 0u;
    }
    __syncthreads();

    bool empty  = (s_empty != 0u);
    int  chunk  = tid & 7;                      // float4 chunk within 32 rules
    int  rowoff = tid >> 3;                     // 0..31
    float4 v0 = reinterpret_cast<const float4*>(s_val)[chunk];
    float4* o4 = reinterpret_cast<float4*>(out);

#pragma unroll
    for (int it = 0; it < 16; it++) {
        int b = b0 + it * 32 + rowoff;
        float4 o;
        if (empty || !g_aflag[b]) {
            o = v0;                             // dominant path
        } else {
            int r0 = rg * 32 + chunk * 4;
            o.x = (s_w[chunk*4+0] == 0u) ? 1.0f : conj_general(b, r0 + 0);
            o.y = (s_w[chunk*4+1] == 0u) ? 1.0f : conj_general(b, r0 + 1);
            o.z = (s_w[chunk*4+2] == 0u) ? 1.0f : conj_general(b, r0 + 2);
            o.w = (s_w[chunk*4+3] == 0u) ? 1.0f : conj_general(b, r0 + 3);
        }
        o4[(size_t)b * 512 + rg * 8 + chunk] = o;
    }
}

// ---------------------------------------------------------------------------
extern "C" void kernel_launch(void* const* d_in, const int* in_sizes, int n_in,
                              void* d_out, int out_size) {
    const float* x = (const float*)d_in[0];   // [BATCH, IN_DIM]
    const float* W = (const float*)d_in[1];   // [IN_DIM, N_RULES]
    float* out = (float*)d_out;               // [BATCH, N_RULES]

    (void)in_sizes; (void)n_in; (void)out_size;

    pack_w_kernel<<<WBLOCKS, 256>>>(W);            // 256 blocks, LDG.128
    pack_x_kernel<<<BATCH / XROWS, 256>>>(x);      // 1024 blocks (early exit)
    out_kernel<<<64 * 16, 256>>>(out);             // 1024 blocks
}